// round 2
// baseline (speedup 1.0000x reference)
#include <cuda_runtime.h>

#define B_   2
#define S_   2048
#define D_   768
#define H_   12
#define DH_  64
#define QKVLD (3 * D_)   // 2304

// Scratch (allocation-free rule: __device__ globals)
__device__ float g_qkv[(size_t)B_ * S_ * 3 * D_];   // [B*S, 3D]
__device__ float g_att[(size_t)B_ * S_ * D_];       // [B*S, D]

// ---------------------------------------------------------------------------
// Tiled SGEMM with bias: C[M,N] = A[M,K] @ Bm[K,N] + bias[N]
// BM=BN=128, BK=8, 256 threads, 8x8 per thread (2x2 quadrants of 4x4).
// Requires M%128==0, N%128==0, K%8==0 (true for all our shapes).
// ---------------------------------------------------------------------------
__global__ __launch_bounds__(256) void sgemm_bias(
    const float* __restrict__ A, const float* __restrict__ Bm,
    const float* __restrict__ bias, float* __restrict__ C,
    int M, int N, int K)
{
    __shared__ float As[8][132];   // pad 4 -> conflict-free transposed stores
    __shared__ float Bs[8][132];

    const int tid  = threadIdx.x;
    const int tx   = tid & 15;
    const int ty   = tid >> 4;
    const int brow = blockIdx.y << 7;
    const int bcol = blockIdx.x << 7;

    const int aRow = tid >> 1;         // 0..127
    const int aCol = (tid & 1) << 2;   // 0 or 4
    const int bRow = tid >> 5;         // 0..7
    const int bCol = (tid & 31) << 2;  // 0..124

    const float* Ap = A  + (size_t)(brow + aRow) * K + aCol;
    const float* Bp = Bm + (size_t)bRow * N + bcol + bCol;

    float acc[2][2][4][4];
#pragma unroll
    for (int p = 0; p < 2; p++)
#pragma unroll
        for (int q = 0; q < 2; q++)
#pragma unroll
            for (int i = 0; i < 4; i++)
#pragma unroll
                for (int j = 0; j < 4; j++) acc[p][q][i][j] = 0.f;

    float4 av = *(const float4*)(Ap);
    float4 bv = *(const float4*)(Bp);

    for (int k0 = 0; k0 < K; k0 += 8) {
        As[aCol + 0][aRow] = av.x;
        As[aCol + 1][aRow] = av.y;
        As[aCol + 2][aRow] = av.z;
        As[aCol + 3][aRow] = av.w;
        *(float4*)&Bs[bRow][bCol] = bv;
        __syncthreads();

        float4 avn = av, bvn = bv;
        if (k0 + 8 < K) {  // register prefetch of next tile
            avn = *(const float4*)(Ap + k0 + 8);
            bvn = *(const float4*)(Bp + (size_t)(k0 + 8) * N);
        }

#pragma unroll
        for (int k = 0; k < 8; k++) {
            float4 a0 = *(const float4*)&As[k][ty << 2];
            float4 a1 = *(const float4*)&As[k][(ty << 2) + 64];
            float4 b0 = *(const float4*)&Bs[k][tx << 2];
            float4 b1 = *(const float4*)&Bs[k][(tx << 2) + 64];
            float ar[2][4] = {{a0.x, a0.y, a0.z, a0.w}, {a1.x, a1.y, a1.z, a1.w}};
            float br[2][4] = {{b0.x, b0.y, b0.z, b0.w}, {b1.x, b1.y, b1.z, b1.w}};
#pragma unroll
            for (int p = 0; p < 2; p++)
#pragma unroll
                for (int i = 0; i < 4; i++)
#pragma unroll
                    for (int q = 0; q < 2; q++)
#pragma unroll
                        for (int j = 0; j < 4; j++)
                            acc[p][q][i][j] += ar[p][i] * br[q][j];
        }
        __syncthreads();
        av = avn; bv = bvn;
    }

#pragma unroll
    for (int p = 0; p < 2; p++)
#pragma unroll
        for (int i = 0; i < 4; i++) {
            int row = brow + (p << 6) + (ty << 2) + i;
#pragma unroll
            for (int q = 0; q < 2; q++) {
                int col = bcol + (q << 6) + (tx << 2);
                float4 o;
                o.x = acc[p][q][i][0] + bias[col + 0];
                o.y = acc[p][q][i][1] + bias[col + 1];
                o.z = acc[p][q][i][2] + bias[col + 2];
                o.w = acc[p][q][i][3] + bias[col + 3];
                *(float4*)&C[(size_t)row * N + col] = o;
            }
        }
}

// ---------------------------------------------------------------------------
// Flash attention, fp32, causal. BM=BN=64, DH=64, 256 threads.
// Q/K tiles stored d-major (transposed) with XOR swizzle on 16B column groups
// so both the transposed stores AND the float4 compute loads are conflict-free.
// P tile stored c-major with the same swizzle. V stored naturally.
// ---------------------------------------------------------------------------
__device__ __forceinline__ int trn_idx(int d, int c) {
    // transposed tile [d][c], 64 floats/row, group-swizzled by (d>>2)
    return (d << 6) + ((((c >> 2) ^ (d >> 2)) & 15) << 2) + (c & 3);
}

__global__ __launch_bounds__(256) void flash_attn(
    const float* __restrict__ qkv, float* __restrict__ out)
{
    extern __shared__ float sm[];
    float* Qs = sm;             // [64][64] transposed swizzled
    float* Ks = sm + 4096;      // [64][64] transposed swizzled
    float* Vs = sm + 8192;      // [64][64] natural [c][d]
    float* Ps = sm + 12288;     // [64][64] transposed swizzled [c][r]

    const int tid  = threadIdx.x;
    const int tx   = tid & 15;
    const int ty   = tid >> 4;
    const int mblk = (int)gridDim.x - 1 - (int)blockIdx.x;  // heavy blocks first
    const int h    = blockIdx.y;
    const int b    = blockIdx.z;
    const int m0   = mblk << 6;

    const float* Qg = qkv + (size_t)b * S_ * QKVLD + h * DH_;
    const float* Kg = Qg + D_;
    const float* Vg = Qg + 2 * D_;

    // Load Q tile transposed + swizzled
#pragma unroll
    for (int l = 0; l < 4; l++) {
        int f4 = (l << 8) + tid;
        int r  = f4 >> 4;
        int d0 = (f4 & 15) << 2;
        float4 v = *(const float4*)&Qg[(size_t)(m0 + r) * QKVLD + d0];
        Qs[trn_idx(d0 + 0, r)] = v.x;
        Qs[trn_idx(d0 + 1, r)] = v.y;
        Qs[trn_idx(d0 + 2, r)] = v.z;
        Qs[trn_idx(d0 + 3, r)] = v.w;
    }

    float m_i[4], l_i[4], o[4][4];
#pragma unroll
    for (int i = 0; i < 4; i++) {
        m_i[i] = -1e30f;
        l_i[i] = 0.f;
#pragma unroll
        for (int j = 0; j < 4; j++) o[i][j] = 0.f;
    }

    for (int nb = 0; nb <= mblk; nb++) {
        const int n0 = nb << 6;
        __syncthreads();  // prior reads of Ks/Vs/Ps done

        // Load K (transposed swizzled) and V (natural)
#pragma unroll
        for (int l = 0; l < 4; l++) {
            int f4 = (l << 8) + tid;
            int c  = f4 >> 4;
            int d0 = (f4 & 15) << 2;
            float4 kv = *(const float4*)&Kg[(size_t)(n0 + c) * QKVLD + d0];
            Ks[trn_idx(d0 + 0, c)] = kv.x;
            Ks[trn_idx(d0 + 1, c)] = kv.y;
            Ks[trn_idx(d0 + 2, c)] = kv.z;
            Ks[trn_idx(d0 + 3, c)] = kv.w;
            float4 vv = *(const float4*)&Vg[(size_t)(n0 + c) * QKVLD + d0];
            *(float4*)&Vs[(c << 6) + d0] = vv;
        }
        __syncthreads();

        // Scores: S = Q K^T (4x4 per thread), K-dim = d
        float s[4][4];
#pragma unroll
        for (int i = 0; i < 4; i++)
#pragma unroll
            for (int j = 0; j < 4; j++) s[i][j] = 0.f;

#pragma unroll 16
        for (int d = 0; d < 64; d++) {
            float4 a  = *(const float4*)&Qs[(d << 6) + (((ty ^ (d >> 2)) & 15) << 2)];
            float4 bb = *(const float4*)&Ks[(d << 6) + (((tx ^ (d >> 2)) & 15) << 2)];
            float avv[4] = {a.x, a.y, a.z, a.w};
            float bvv[4] = {bb.x, bb.y, bb.z, bb.w};
#pragma unroll
            for (int i = 0; i < 4; i++)
#pragma unroll
                for (int j = 0; j < 4; j++)
                    s[i][j] += avv[i] * bvv[j];
        }

        // Scale + causal mask (diagonal block only)
        const float scale = 0.125f;
        if (nb == mblk) {
#pragma unroll
            for (int i = 0; i < 4; i++)
#pragma unroll
                for (int j = 0; j < 4; j++) {
                    int rloc = (ty << 2) + i, cloc = (tx << 2) + j;
                    s[i][j] = (cloc > rloc) ? -1e30f : s[i][j] * scale;
                }
        } else {
#pragma unroll
            for (int i = 0; i < 4; i++)
#pragma unroll
                for (int j = 0; j < 4; j++) s[i][j] *= scale;
        }

        // Online softmax (row stats reduced over the 16 tx-threads via shfl)
#pragma unroll
        for (int i = 0; i < 4; i++) {
            float mx = fmaxf(fmaxf(s[i][0], s[i][1]), fmaxf(s[i][2], s[i][3]));
#pragma unroll
            for (int off = 8; off > 0; off >>= 1)
                mx = fmaxf(mx, __shfl_xor_sync(0xffffffffu, mx, off));
            float mnew  = fmaxf(m_i[i], mx);
            float alpha = __expf(m_i[i] - mnew);
            float p0 = __expf(s[i][0] - mnew);
            float p1 = __expf(s[i][1] - mnew);
            float p2 = __expf(s[i][2] - mnew);
            float p3 = __expf(s[i][3] - mnew);
            float rs = (p0 + p1) + (p2 + p3);
#pragma unroll
            for (int off = 8; off > 0; off >>= 1)
                rs += __shfl_xor_sync(0xffffffffu, rs, off);
            l_i[i] = l_i[i] * alpha + rs;
            m_i[i] = mnew;
#pragma unroll
            for (int j = 0; j < 4; j++) o[i][j] *= alpha;
            // Store P transposed swizzled: column c=tx*4+j, row r=ty*4+i
            Ps[(((tx << 2) + 0) << 6) + (((ty ^ tx) & 15) << 2) + i] = p0;
            Ps[(((tx << 2) + 1) << 6) + (((ty ^ tx) & 15) << 2) + i] = p1;
            Ps[(((tx << 2) + 2) << 6) + (((ty ^ tx) & 15) << 2) + i] = p2;
            Ps[(((tx << 2) + 3) << 6) + (((ty ^ tx) & 15) << 2) + i] = p3;
        }
        __syncthreads();

        // O += P @ V  (K-dim = c)
#pragma unroll 16
        for (int c = 0; c < 64; c++) {
            float4 a  = *(const float4*)&Ps[(c << 6) + (((ty ^ (c >> 2)) & 15) << 2)];
            float4 bb = *(const float4*)&Vs[(c << 6) + (tx << 2)];
            float avv[4] = {a.x, a.y, a.z, a.w};
            float bvv[4] = {bb.x, bb.y, bb.z, bb.w};
#pragma unroll
            for (int i = 0; i < 4; i++)
#pragma unroll
                for (int j = 0; j < 4; j++)
                    o[i][j] += avv[i] * bvv[j];
        }
    }

    // Epilogue: normalize and write merged-head layout [B*S, D]
#pragma unroll
    for (int i = 0; i < 4; i++) {
        float inv = 1.0f / l_i[i];
        float4 ov;
        ov.x = o[i][0] * inv;
        ov.y = o[i][1] * inv;
        ov.z = o[i][2] * inv;
        ov.w = o[i][3] * inv;
        size_t row = (size_t)b * S_ + m0 + (ty << 2) + i;
        *(float4*)&out[row * D_ + h * DH_ + (tx << 2)] = ov;
    }
}

// ---------------------------------------------------------------------------
extern "C" void kernel_launch(void* const* d_in, const int* in_sizes, int n_in,
                              void* d_out, int out_size)
{
    (void)in_sizes; (void)n_in; (void)out_size;
    const float* x    = (const float*)d_in[0];
    // d_in[1] = attn_mask (static causal; encoded directly in the kernel)
    const float* Wqkv = (const float*)d_in[2];
    const float* bqkv = (const float*)d_in[3];
    const float* Wp   = (const float*)d_in[4];
    const float* bp   = (const float*)d_in[5];
    float* out = (float*)d_out;

    float* qkv = nullptr;
    float* att = nullptr;
    cudaGetSymbolAddress((void**)&qkv, g_qkv);
    cudaGetSymbolAddress((void**)&att, g_att);

    cudaFuncSetAttribute(flash_attn,
                         cudaFuncAttributeMaxDynamicSharedMemorySize, 65536);

    const int M = B_ * S_;  // 4096

    // QKV projection: [4096,768] @ [768,2304] + b
    sgemm_bias<<<dim3(QKVLD / 128, M / 128), 256>>>(x, Wqkv, bqkv, qkv, M, QKVLD, D_);

    // Causal flash attention -> merged heads [4096, 768]
    flash_attn<<<dim3(S_ / 64, H_, B_), 256, 65536>>>(qkv, att);

    // Output projection: [4096,768] @ [768,768] + b
    sgemm_bias<<<dim3(D_ / 128, M / 128), 256>>>(att, Wp, bp, out, M, D_, D_);
}